// round 5
// baseline (speedup 1.0000x reference)
#include <cuda_runtime.h>
#include <cstdint>

// MessagePassing scatter-add:  out[dst[e], :] += x[src[e], :]
// x: [N, 64] f32, edge_index: [2, E] int32 (harness-narrowed), out: [N, 64] f32.
//
// R3: ILP batching. Each warp = 2 edge-slots x 16 chunk-lanes; each thread
// processes U=4 edges with indices hoisted, gathers issued back-to-back
// (MLP=4), then 4 vector no-return reductions.

static constexpr int D = 64;
static constexpr int CHUNKS = D / 4;   // 16 float4 per row
static constexpr int U = 4;            // edges per thread
static constexpr int EDGES_PER_WARP = 2 * U;

__global__ void __launch_bounds__(256) mp_scatter_kernel(
    const float4* __restrict__ x,
    const int* __restrict__ src,
    const int* __restrict__ dst,
    float* __restrict__ out,
    long long E) {
    const int lane = threadIdx.x & 31;
    const int half = lane >> 4;          // edge slot within warp (0/1)
    const int c = lane & 15;             // float4 chunk within row
    const long long w = ((long long)blockIdx.x * blockDim.x + threadIdx.x) >> 5;
    const long long e_base = w * EDGES_PER_WARP + half;

    // 1) hoist indices (independent loads; uniform across each 16-lane half)
    int s[U], d[U];
    bool ok[U];
#pragma unroll
    for (int i = 0; i < U; i++) {
        long long e = e_base + 2 * i;
        ok[i] = (e < E);
        long long ec = ok[i] ? e : 0;
        s[i] = __ldg(&src[ec]);
        d[i] = __ldg(&dst[ec]);
    }

    // 2) gathers in flight (MLP = U)
    float4 v[U];
#pragma unroll
    for (int i = 0; i < U; i++) {
        v[i] = __ldg(&x[(long long)s[i] * CHUNKS + c]);
    }

    // 3) vector no-return reductions
#pragma unroll
    for (int i = 0; i < U; i++) {
        if (ok[i]) {
            float* p = out + (long long)d[i] * D + c * 4;
            asm volatile("red.global.add.v4.f32 [%0], {%1, %2, %3, %4};"
                         :: "l"(p), "f"(v[i].x), "f"(v[i].y), "f"(v[i].z), "f"(v[i].w)
                         : "memory");
        }
    }
}

extern "C" void kernel_launch(void* const* d_in, const int* in_sizes, int n_in,
                              void* d_out, int out_size) {
    const float4* x = (const float4*)d_in[0];    // [N, 64] f32 as float4[N*16]
    const int* ei = (const int*)d_in[1];         // [2, E] int32
    float* out = (float*)d_out;

    long long E = (long long)in_sizes[1] / 2;
    const int* src = ei;
    const int* dst = ei + E;

    cudaMemsetAsync(d_out, 0, (size_t)out_size * sizeof(float), 0);

    // one warp per EDGES_PER_WARP edges
    long long warps = (E + EDGES_PER_WARP - 1) / EDGES_PER_WARP;
    long long threads_total = warps * 32;
    int threads = 256;
    long long blocks = (threads_total + threads - 1) / threads;
    mp_scatter_kernel<<<(unsigned)blocks, threads>>>(x, src, dst, out, E);
}

// round 6
// speedup vs baseline: 1.0127x; 1.0127x over previous
#include <cuda_runtime.h>
#include <cstdint>

// MessagePassing scatter-add:  out[dst[e], :] += x[src[e], :]
// x: [N, 64] f32, edge_index: [2, E] int32 (harness-narrowed), out: [N, 64] f32.
//
// R5: warp = 2 halves x 16 chunk-lanes. Each half owns 8 CONTIGUOUS edges;
// indices loaded as int4 (uniform-broadcast within the half, 1 wavefront each),
// 8 gathers in flight per thread, then 8 vector no-return reductions.

static constexpr int D = 64;
static constexpr int CHUNKS = D / 4;     // 16 float4 per row
static constexpr int U = 8;              // edges per half (= per thread)
static constexpr int EDGES_PER_WARP = 2 * U;   // 16

__global__ void __launch_bounds__(256) mp_scatter_vec(
    const float4* __restrict__ x,
    const int* __restrict__ src,
    const int* __restrict__ dst,
    float* __restrict__ out,
    long long n_warps) {
    const long long t = (long long)blockIdx.x * blockDim.x + threadIdx.x;
    const long long w = t >> 5;
    if (w >= n_warps) return;

    const int lane = (int)(threadIdx.x & 31);
    const int h = lane >> 4;     // half: which 8-edge group
    const int c = lane & 15;     // float4 chunk within row

    const long long base = w * EDGES_PER_WARP + (long long)h * U;

    // Vectorized index loads: uniform within each 16-lane half -> 1 wf each.
    int4 sa = __ldg((const int4*)(src + base));
    int4 sb = __ldg((const int4*)(src + base + 4));
    int4 da = __ldg((const int4*)(dst + base));
    int4 db = __ldg((const int4*)(dst + base + 4));
    int s[U] = {sa.x, sa.y, sa.z, sa.w, sb.x, sb.y, sb.z, sb.w};
    int d[U] = {da.x, da.y, da.z, da.w, db.x, db.y, db.z, db.w};

    // 8 independent gathers in flight (MLP = 8).
    float4 v[U];
#pragma unroll
    for (int i = 0; i < U; i++) {
        v[i] = __ldg(&x[(long long)s[i] * CHUNKS + c]);
    }

    // 8 vector no-return reductions.
#pragma unroll
    for (int i = 0; i < U; i++) {
        float* p = out + (long long)d[i] * D + c * 4;
        asm volatile("red.global.add.v4.f32 [%0], {%1, %2, %3, %4};"
                     :: "l"(p), "f"(v[i].x), "f"(v[i].y), "f"(v[i].z), "f"(v[i].w)
                     : "memory");
    }
}

// Scalar tail for E not divisible by EDGES_PER_WARP (not hit for E=1.6M).
__global__ void mp_scatter_tail(const float4* __restrict__ x,
                                const int* __restrict__ src,
                                const int* __restrict__ dst,
                                float* __restrict__ out,
                                long long e0, long long E) {
    long long gid = (long long)blockIdx.x * blockDim.x + threadIdx.x;
    long long e = e0 + (gid >> 4);
    if (e >= E) return;
    int c = (int)(gid & 15);
    int s = __ldg(&src[e]);
    int d = __ldg(&dst[e]);
    float4 v = __ldg(&x[(long long)s * CHUNKS + c]);
    float* p = out + (long long)d * D + c * 4;
    asm volatile("red.global.add.v4.f32 [%0], {%1, %2, %3, %4};"
                 :: "l"(p), "f"(v.x), "f"(v.y), "f"(v.z), "f"(v.w)
                 : "memory");
}

extern "C" void kernel_launch(void* const* d_in, const int* in_sizes, int n_in,
                              void* d_out, int out_size) {
    const float4* x = (const float4*)d_in[0];    // [N, 64] f32 as float4[N*16]
    const int* ei = (const int*)d_in[1];         // [2, E] int32
    float* out = (float*)d_out;

    long long E = (long long)in_sizes[1] / 2;
    const int* src = ei;
    const int* dst = ei + E;

    cudaMemsetAsync(d_out, 0, (size_t)out_size * sizeof(float), 0);

    long long E_main = E & ~((long long)EDGES_PER_WARP - 1);
    long long n_warps = E_main / EDGES_PER_WARP;
    long long threads_total = n_warps * 32;
    int threads = 256;
    long long blocks = (threads_total + threads - 1) / threads;
    if (blocks > 0)
        mp_scatter_vec<<<(unsigned)blocks, threads>>>(x, src, dst, out, n_warps);

    long long tail = E - E_main;
    if (tail > 0) {
        long long titems = tail * CHUNKS;
        int tthreads = 256;
        long long tblocks = (titems + tthreads - 1) / tthreads;
        mp_scatter_tail<<<(unsigned)tblocks, tthreads>>>(x, src, dst, out, E_main, E);
    }
}

// round 7
// speedup vs baseline: 1.1423x; 1.1281x over previous
#include <cuda_runtime.h>
#include <cstdint>

// MessagePassing scatter-add:  out[dst[e], :] += x[src[e], :]
// x: [N, 64] f32, edge_index: [2, E] int32 (harness-narrowed), out: [N, 64] f32.
//
// R6: CSR pull-mode. Evidence from R3-R5: kernel is pinned at the LTS byte
// throughput wall (~10.8 TB/s); only traffic reduction helps. Pipeline:
//   1. zero counts            4. chunk-local scan -> offsets, cursor
//   2. histogram of dst       5. scatter src -> perm[atomic cursor]
//   3. scan partials          6. pull: per-node gather+sum, single out write
// Removes the 409MB RED stream (write out once: 25.6MB) and the out memset.

static constexpr int D = 64;
static constexpr int CHUNKS = D / 4;          // 16 float4 per row
static constexpr int N_MAX = 100000;
static constexpr long long E_MAX = 1600000;
static constexpr int SCAN_CHUNK = 1024;       // elements per scan block
static constexpr int SCAN_BLOCKS = (N_MAX + SCAN_CHUNK - 1) / SCAN_CHUNK;  // 98

__device__ int g_counts[N_MAX];
__device__ int g_offsets[N_MAX + 1];
__device__ int g_cursor[N_MAX];
__device__ int g_partials[SCAN_BLOCKS];
__device__ int g_perm[E_MAX];

// ---------- build kernels ----------

__global__ void k_zero_counts(int n) {
    int i = blockIdx.x * blockDim.x + threadIdx.x;
    if (i < n) g_counts[i] = 0;
}

__global__ void k_hist(const int* __restrict__ dst, long long E) {
    long long e = (long long)blockIdx.x * blockDim.x + threadIdx.x;
    if (e < E) atomicAdd(&g_counts[__ldg(&dst[e])], 1);  // no-return -> RED
}

// per-chunk sums -> g_partials
__global__ void k_scan1(int n) {
    __shared__ int sm[32];
    int base = blockIdx.x * SCAN_CHUNK + threadIdx.x * 4;
    int s = 0;
#pragma unroll
    for (int k = 0; k < 4; k++)
        if (base + k < n) s += g_counts[base + k];
    // block reduce
    int lane = threadIdx.x & 31, wid = threadIdx.x >> 5;
#pragma unroll
    for (int o = 16; o > 0; o >>= 1) s += __shfl_down_sync(~0u, s, o);
    if (lane == 0) sm[wid] = s;
    __syncthreads();
    if (wid == 0) {
        s = (lane < (blockDim.x >> 5)) ? sm[lane] : 0;
#pragma unroll
        for (int o = 16; o > 0; o >>= 1) s += __shfl_down_sync(~0u, s, o);
        if (lane == 0) g_partials[blockIdx.x] = s;
    }
}

// exclusive scan of partials (small), also writes offsets[n] = E
__global__ void k_scan2(int n, int E) {
    __shared__ int sm[SCAN_BLOCKS];
    int t = threadIdx.x;
    for (int i = t; i < SCAN_BLOCKS; i += blockDim.x) sm[i] = g_partials[i];
    __syncthreads();
    if (t == 0) {
        int run = 0;
        for (int i = 0; i < SCAN_BLOCKS; i++) { int v = sm[i]; sm[i] = run; run += v; }
        g_offsets[n] = E;
    }
    __syncthreads();
    for (int i = t; i < SCAN_BLOCKS; i += blockDim.x) g_partials[i] = sm[i];
}

// chunk-local exclusive scan + partial base -> offsets + cursor
__global__ void k_scan3(int n) {
    __shared__ int sm[32];
    int t = threadIdx.x;
    int lane = t & 31, wid = t >> 5;
    int idx0 = blockIdx.x * SCAN_CHUNK + t * 4;
    int v[4];
    int tsum = 0;
#pragma unroll
    for (int k = 0; k < 4; k++) {
        v[k] = (idx0 + k < n) ? g_counts[idx0 + k] : 0;
        tsum += v[k];
    }
    // block exclusive scan of tsum
    int x = tsum;
#pragma unroll
    for (int o = 1; o < 32; o <<= 1) {
        int y = __shfl_up_sync(~0u, x, o);
        if (lane >= o) x += y;
    }
    if (lane == 31) sm[wid] = x;
    __syncthreads();
    if (wid == 0) {
        int w = (lane < (blockDim.x >> 5)) ? sm[lane] : 0;
#pragma unroll
        for (int o = 1; o < 32; o <<= 1) {
            int y = __shfl_up_sync(~0u, w, o);
            if (lane >= o) w += y;
        }
        sm[lane] = w;
    }
    __syncthreads();
    int excl = ((wid == 0) ? 0 : sm[wid - 1]) + (x - tsum);
    int run = g_partials[blockIdx.x] + excl;
#pragma unroll
    for (int k = 0; k < 4; k++) {
        if (idx0 + k < n) {
            g_offsets[idx0 + k] = run;
            g_cursor[idx0 + k] = run;
            run += v[k];
        }
    }
}

__global__ void k_scatter(const int* __restrict__ src,
                          const int* __restrict__ dst, long long E) {
    long long e = (long long)blockIdx.x * blockDim.x + threadIdx.x;
    if (e < E) {
        int d = __ldg(&dst[e]);
        int pos = atomicAdd(&g_cursor[d], 1);
        g_perm[pos] = __ldg(&src[e]);
    }
}

// ---------- main pull kernel ----------
// half-warp (16 lanes) per node; lane c accumulates float4 chunk c.
__global__ void __launch_bounds__(256) k_gather(const float4* __restrict__ x,
                                                float4* __restrict__ out,
                                                int n) {
    long long t = (long long)blockIdx.x * blockDim.x + threadIdx.x;
    long long node = t >> 4;
    int c = (int)(t & 15);
    if (node >= n) return;

    int beg = __ldg(&g_offsets[node]);
    int end = __ldg(&g_offsets[node + 1]);

    float4 acc = make_float4(0.f, 0.f, 0.f, 0.f);
    int j = beg;
    for (; j + 4 <= end; j += 4) {
        int s0 = __ldg(&g_perm[j + 0]);
        int s1 = __ldg(&g_perm[j + 1]);
        int s2 = __ldg(&g_perm[j + 2]);
        int s3 = __ldg(&g_perm[j + 3]);
        float4 a = __ldg(&x[(long long)s0 * CHUNKS + c]);
        float4 b = __ldg(&x[(long long)s1 * CHUNKS + c]);
        float4 cc = __ldg(&x[(long long)s2 * CHUNKS + c]);
        float4 d = __ldg(&x[(long long)s3 * CHUNKS + c]);
        acc.x += a.x + b.x + cc.x + d.x;
        acc.y += a.y + b.y + cc.y + d.y;
        acc.z += a.z + b.z + cc.z + d.z;
        acc.w += a.w + b.w + cc.w + d.w;
    }
    for (; j < end; j++) {
        int s = __ldg(&g_perm[j]);
        float4 a = __ldg(&x[(long long)s * CHUNKS + c]);
        acc.x += a.x; acc.y += a.y; acc.z += a.z; acc.w += a.w;
    }
    out[node * CHUNKS + c] = acc;   // every row written (zeros for deg-0 nodes)
}

// ---------- fallback (R5 scatter path) for unexpected shapes ----------
__global__ void mp_scatter_tail(const float4* __restrict__ x,
                                const int* __restrict__ src,
                                const int* __restrict__ dst,
                                float* __restrict__ out,
                                long long e0, long long E) {
    long long gid = (long long)blockIdx.x * blockDim.x + threadIdx.x;
    long long e = e0 + (gid >> 4);
    if (e >= E) return;
    int c = (int)(gid & 15);
    int s = __ldg(&src[e]);
    int d = __ldg(&dst[e]);
    float4 v = __ldg(&x[(long long)s * CHUNKS + c]);
    float* p = out + (long long)d * D + c * 4;
    asm volatile("red.global.add.v4.f32 [%0], {%1, %2, %3, %4};"
                 :: "l"(p), "f"(v.x), "f"(v.y), "f"(v.z), "f"(v.w)
                 : "memory");
}

extern "C" void kernel_launch(void* const* d_in, const int* in_sizes, int n_in,
                              void* d_out, int out_size) {
    const float4* x = (const float4*)d_in[0];    // [N, 64] f32 as float4[N*16]
    const int* ei = (const int*)d_in[1];         // [2, E] int32
    long long E = (long long)in_sizes[1] / 2;
    const int* src = ei;
    const int* dst = ei + E;
    int N = out_size / D;

    if (E > E_MAX || N > N_MAX) {
        // fallback: RED scatter
        cudaMemsetAsync(d_out, 0, (size_t)out_size * sizeof(float), 0);
        long long items = E * CHUNKS;
        long long blocks = (items + 255) / 256;
        mp_scatter_tail<<<(unsigned)blocks, 256>>>(x, src, dst, (float*)d_out, 0, E);
        return;
    }

    int eb = (int)((E + 255) / 256);

    k_zero_counts<<<(N + 255) / 256, 256>>>(N);
    k_hist<<<eb, 256>>>(dst, E);
    k_scan1<<<SCAN_BLOCKS, 256>>>(N);
    k_scan2<<<1, 128>>>(N, (int)E);
    k_scan3<<<SCAN_BLOCKS, 256>>>(N);
    k_scatter<<<eb, 256>>>(src, dst, E);

    long long gthreads = (long long)N * CHUNKS;
    k_gather<<<(unsigned)((gthreads + 255) / 256), 256>>>(x, (float4*)d_out, N);
}

// round 8
// speedup vs baseline: 1.2064x; 1.0561x over previous
#include <cuda_runtime.h>
#include <cstdint>

// MessagePassing scatter-add:  out[dst[e], :] += x[src[e], :]
// x: [N, 64] f32, edge_index: [2, E] int32 (harness-narrowed), out: [N, 64] f32.
//
// R7: CSR pull-mode, build phase slimmed to 4 kernels + gather:
//   1. hist   (int4-vectorized dst histogram, RED atomics)
//   2. scan1  (per-1024-chunk sums -> partials)
//   3. scan3' (each block scans ALL 98 partials redundantly for its base,
//              local exclusive scan -> offsets+cursor, re-zeros counts)
//   4. scatter (int4-vectorized, perm[cursor++] = src)
//   5. gather (half-warp per node, registers accumulate, single out write)
// g_counts relies on zero-init at module load; scan3' restores zeros each call.

static constexpr int D = 64;
static constexpr int CHUNKS = D / 4;          // 16 float4 per row
static constexpr int N_MAX = 100000;
static constexpr long long E_MAX = 1600000;
static constexpr int SCAN_CHUNK = 1024;       // elements per scan block
static constexpr int SCAN_BLOCKS = (N_MAX + SCAN_CHUNK - 1) / SCAN_CHUNK;  // 98

__device__ int g_counts[N_MAX];               // zero-init; invariant: zero on entry
__device__ int g_offsets[N_MAX + 1];
__device__ int g_cursor[N_MAX];
__device__ int g_partials[SCAN_BLOCKS];
__device__ int g_perm[E_MAX];

// ---------- 1. histogram (vectorized) ----------
__global__ void k_hist(const int* __restrict__ dst, long long E) {
    long long q = (long long)blockIdx.x * blockDim.x + threadIdx.x;
    long long e = q * 4;
    if (e + 4 <= E) {
        int4 d4 = __ldg((const int4*)(dst + e));
        atomicAdd(&g_counts[d4.x], 1);
        atomicAdd(&g_counts[d4.y], 1);
        atomicAdd(&g_counts[d4.z], 1);
        atomicAdd(&g_counts[d4.w], 1);
    } else {
        for (long long i = e; i < E; i++) atomicAdd(&g_counts[__ldg(&dst[i])], 1);
    }
}

// ---------- 2. per-chunk sums -> g_partials ----------
__global__ void k_scan1(int n) {
    __shared__ int sm[32];
    int base = blockIdx.x * SCAN_CHUNK + threadIdx.x * 4;
    int s = 0;
#pragma unroll
    for (int k = 0; k < 4; k++)
        if (base + k < n) s += g_counts[base + k];
    int lane = threadIdx.x & 31, wid = threadIdx.x >> 5;
#pragma unroll
    for (int o = 16; o > 0; o >>= 1) s += __shfl_down_sync(~0u, s, o);
    if (lane == 0) sm[wid] = s;
    __syncthreads();
    if (wid == 0) {
        s = (lane < (blockDim.x >> 5)) ? sm[lane] : 0;
#pragma unroll
        for (int o = 16; o > 0; o >>= 1) s += __shfl_down_sync(~0u, s, o);
        if (lane == 0) g_partials[blockIdx.x] = s;
    }
}

// ---------- 3. fused base-scan + local scan + counts re-zero ----------
__global__ void k_scan3(int n, int E) {
    __shared__ int sp[SCAN_BLOCKS];   // all partials
    __shared__ int sm[33];
    int t = threadIdx.x;
    int lane = t & 31, wid = t >> 5;

    // every block redundantly loads all partials (L2 hit) and scans its base
    if (t < SCAN_BLOCKS) sp[t] = g_partials[t];
    __syncthreads();
    if (t == 0) {
        int run = 0;
        for (int i = 0; i < SCAN_BLOCKS; i++) { int v = sp[i]; sp[i] = run; run += v; }
    }
    __syncthreads();
    int block_base = sp[blockIdx.x];

    int idx0 = blockIdx.x * SCAN_CHUNK + t * 4;
    int v[4];
    int tsum = 0;
#pragma unroll
    for (int k = 0; k < 4; k++) {
        v[k] = (idx0 + k < n) ? g_counts[idx0 + k] : 0;
        tsum += v[k];
    }
    // re-zero counts for the next call (invariant)
#pragma unroll
    for (int k = 0; k < 4; k++)
        if (idx0 + k < n) g_counts[idx0 + k] = 0;

    // block-level exclusive scan of tsum
    int x = tsum;
#pragma unroll
    for (int o = 1; o < 32; o <<= 1) {
        int y = __shfl_up_sync(~0u, x, o);
        if (lane >= o) x += y;
    }
    if (lane == 31) sm[wid] = x;
    __syncthreads();
    if (wid == 0) {
        int w = (lane < (blockDim.x >> 5)) ? sm[lane] : 0;
#pragma unroll
        for (int o = 1; o < 32; o <<= 1) {
            int y = __shfl_up_sync(~0u, w, o);
            if (lane >= o) w += y;
        }
        sm[lane] = w;
    }
    __syncthreads();
    int excl = ((wid == 0) ? 0 : sm[wid - 1]) + (x - tsum);
    int run = block_base + excl;
#pragma unroll
    for (int k = 0; k < 4; k++) {
        if (idx0 + k < n) {
            g_offsets[idx0 + k] = run;
            g_cursor[idx0 + k] = run;
            run += v[k];
        }
    }
    if (blockIdx.x == 0 && t == 0) g_offsets[n] = E;
}

// ---------- 4. scatter (vectorized) ----------
__global__ void k_scatter(const int* __restrict__ src,
                          const int* __restrict__ dst, long long E) {
    long long q = (long long)blockIdx.x * blockDim.x + threadIdx.x;
    long long e = q * 4;
    if (e + 4 <= E) {
        int4 d4 = __ldg((const int4*)(dst + e));
        int4 s4 = __ldg((const int4*)(src + e));
        g_perm[atomicAdd(&g_cursor[d4.x], 1)] = s4.x;
        g_perm[atomicAdd(&g_cursor[d4.y], 1)] = s4.y;
        g_perm[atomicAdd(&g_cursor[d4.z], 1)] = s4.z;
        g_perm[atomicAdd(&g_cursor[d4.w], 1)] = s4.w;
    } else {
        for (long long i = e; i < E; i++) {
            int d = __ldg(&dst[i]);
            g_perm[atomicAdd(&g_cursor[d], 1)] = __ldg(&src[i]);
        }
    }
}

// ---------- 5. pull gather: half-warp per node ----------
__global__ void __launch_bounds__(256) k_gather(const float4* __restrict__ x,
                                                float4* __restrict__ out,
                                                int n) {
    long long t = (long long)blockIdx.x * blockDim.x + threadIdx.x;
    long long node = t >> 4;
    int c = (int)(t & 15);
    if (node >= n) return;

    int beg = __ldg(&g_offsets[node]);
    int end = __ldg(&g_offsets[node + 1]);

    float4 acc = make_float4(0.f, 0.f, 0.f, 0.f);
    int j = beg;
    for (; j + 4 <= end; j += 4) {
        int s0 = __ldg(&g_perm[j + 0]);
        int s1 = __ldg(&g_perm[j + 1]);
        int s2 = __ldg(&g_perm[j + 2]);
        int s3 = __ldg(&g_perm[j + 3]);
        float4 a = __ldg(&x[(long long)s0 * CHUNKS + c]);
        float4 b = __ldg(&x[(long long)s1 * CHUNKS + c]);
        float4 cc = __ldg(&x[(long long)s2 * CHUNKS + c]);
        float4 d = __ldg(&x[(long long)s3 * CHUNKS + c]);
        acc.x += a.x + b.x + cc.x + d.x;
        acc.y += a.y + b.y + cc.y + d.y;
        acc.z += a.z + b.z + cc.z + d.z;
        acc.w += a.w + b.w + cc.w + d.w;
    }
    for (; j < end; j++) {
        int s = __ldg(&g_perm[j]);
        float4 a = __ldg(&x[(long long)s * CHUNKS + c]);
        acc.x += a.x; acc.y += a.y; acc.z += a.z; acc.w += a.w;
    }
    out[node * CHUNKS + c] = acc;
}

// ---------- fallback scatter path ----------
__global__ void mp_scatter_tail(const float4* __restrict__ x,
                                const int* __restrict__ src,
                                const int* __restrict__ dst,
                                float* __restrict__ out,
                                long long e0, long long E) {
    long long gid = (long long)blockIdx.x * blockDim.x + threadIdx.x;
    long long e = e0 + (gid >> 4);
    if (e >= E) return;
    int c = (int)(gid & 15);
    int s = __ldg(&src[e]);
    int d = __ldg(&dst[e]);
    float4 v = __ldg(&x[(long long)s * CHUNKS + c]);
    float* p = out + (long long)d * D + c * 4;
    asm volatile("red.global.add.v4.f32 [%0], {%1, %2, %3, %4};"
                 :: "l"(p), "f"(v.x), "f"(v.y), "f"(v.z), "f"(v.w)
                 : "memory");
}

extern "C" void kernel_launch(void* const* d_in, const int* in_sizes, int n_in,
                              void* d_out, int out_size) {
    const float4* x = (const float4*)d_in[0];    // [N, 64] f32 as float4[N*16]
    const int* ei = (const int*)d_in[1];         // [2, E] int32
    long long E = (long long)in_sizes[1] / 2;
    const int* src = ei;
    const int* dst = ei + E;
    int N = out_size / D;

    if (E > E_MAX || N > N_MAX) {
        cudaMemsetAsync(d_out, 0, (size_t)out_size * sizeof(float), 0);
        long long items = E * CHUNKS;
        long long blocks = (items + 255) / 256;
        mp_scatter_tail<<<(unsigned)blocks, 256>>>(x, src, dst, (float*)d_out, 0, E);
        return;
    }

    long long quads = (E + 3) / 4;
    int eb = (int)((quads + 255) / 256);

    k_hist<<<eb, 256>>>(dst, E);
    k_scan1<<<SCAN_BLOCKS, 256>>>(N);
    k_scan3<<<SCAN_BLOCKS, 256>>>(N, (int)E);
    k_scatter<<<eb, 256>>>(src, dst, E);

    long long gthreads = (long long)N * CHUNKS;
    k_gather<<<(unsigned)((gthreads + 255) / 256), 256>>>(x, (float4*)d_out, N);
}